// round 13
// baseline (speedup 1.0000x reference)
#include <cuda_runtime.h>
#include <cuda_bf16.h>
#include <cstdint>

#define N_NODES 25000
#define N_EDGES 400000
#define DF      128
#define N_GRAPHS 512
#define D_OUT   10

typedef unsigned long long ull;

// ---------------- scratch (device globals; no runtime alloc allowed) --------
// g_deg is zero at module load and re-zeroed by scan_kernel each launch.
__device__ __align__(16) int   g_deg[N_NODES];
__device__ __align__(16) int   g_rowptr[N_NODES + 1];
__device__ __align__(16) int   g_cursor[N_NODES];
__device__ __align__(16) int   g_esrc[N_EDGES];
__device__ __align__(16) float g_agg[N_NODES * DF];
__device__ __align__(16) float g_h0[N_NODES * DF];
// bf16 hi/lo weight images, [n][k] row-major, 6 matrices (layer*2 + {W1,W2})
__device__ __align__(16) unsigned short g_wimg_hi[6 * 16384];
__device__ __align__(16) unsigned short g_wimg_lo[6 * 16384];

// ---------------- helpers -----------------------------------------------------
__device__ __forceinline__ uint32_t smem_to_u32(const void* p) {
    uint32_t a;
    asm("{ .reg .u64 t; cvta.to.shared.u64 t, %1; cvt.u32.u64 %0, t; }"
        : "=r"(a) : "l"(p));
    return a;
}
__device__ __forceinline__ void ldsm_x4(uint32_t* r, uint32_t addr) {
    asm volatile("ldmatrix.sync.aligned.m8n8.x4.shared.b16 {%0,%1,%2,%3}, [%4];"
        : "=r"(r[0]), "=r"(r[1]), "=r"(r[2]), "=r"(r[3]) : "r"(addr));
}
__device__ __forceinline__ void ldsm_x2(uint32_t* r, uint32_t addr) {
    asm volatile("ldmatrix.sync.aligned.m8n8.x2.shared.b16 {%0,%1}, [%2];"
        : "=r"(r[0]), "=r"(r[1]) : "r"(addr));
}
__device__ __forceinline__ void mma_bf16(float* c, const uint32_t* a, const uint32_t* b) {
    asm volatile("mma.sync.aligned.m16n8k16.row.col.f32.bf16.bf16.f32 "
        "{%0,%1,%2,%3}, {%4,%5,%6,%7}, {%8,%9}, {%0,%1,%2,%3};"
        : "+f"(c[0]), "+f"(c[1]), "+f"(c[2]), "+f"(c[3])
        : "r"(a[0]), "r"(a[1]), "r"(a[2]), "r"(a[3]), "r"(b[0]), "r"(b[1]));
}
__device__ __forceinline__ uint32_t bf2_bits(__nv_bfloat162 v) {
    return *reinterpret_cast<uint32_t*>(&v);
}
// packed fp32x2 ops (bit-exact fp32 lanes, 1 instruction per 2 floats)
#define ADD2(d, a, b) \
    asm("add.rn.f32x2 %0, %1, %2;" : "=l"(d) : "l"(a), "l"(b))
#define MUL2(d, a, b) \
    asm("mul.rn.f32x2 %0, %1, %2;" : "=l"(d) : "l"(a), "l"(b))
#define DUP2(d, f) \
    asm("mov.b64 %0, {%1, %1};" : "=l"(d) : "r"(__float_as_uint(f)))

// ---------------- hist + weight prep (independent elementwise work) ----------
// g_deg is guaranteed zero on entry (module load / previous scan_kernel).
__global__ void histprep_kernel(const int* __restrict__ dst,
                                const float* __restrict__ W1,
                                const float* __restrict__ W2) {
    int e = blockIdx.x * blockDim.x + threadIdx.x;
    if (e < N_EDGES / 4) {
        int4 d = ((const int4*)dst)[e];
        atomicAdd(&g_deg[d.x], 1);
        atomicAdd(&g_deg[d.y], 1);
        atomicAdd(&g_deg[d.z], 1);
        atomicAdd(&g_deg[d.w], 1);
    }
    if (e < 6 * 16384) {
        int mat = e >> 14, r = e & 16383;
        int k = r & 127, n = r >> 7;
        int layer = mat >> 1;
        const float* W = (mat & 1) ? W2 : W1;
        float v = W[layer * 16384 + k * 128 + n];
        __nv_bfloat16 hb = __float2bfloat16(v);
        __nv_bfloat16 lb = __float2bfloat16(v - __bfloat162float(hb));
        g_wimg_hi[mat * 16384 + n * 128 + k] = *reinterpret_cast<unsigned short*>(&hb);
        g_wimg_lo[mat * 16384 + n * 128 + k] = *reinterpret_cast<unsigned short*>(&lb);
    }
}

__global__ void scan_kernel() {
    __shared__ int warp_sums[32];
    __shared__ int s_base;
    int t = threadIdx.x, lane = t & 31, w = t >> 5;
    if (t == 0) s_base = 0;
    __syncthreads();
    for (int base = 0; base < N_NODES; base += 1024) {
        int i = base + t;
        int v = (i < N_NODES) ? g_deg[i] : 0;
        if (i < N_NODES) g_deg[i] = 0;   // leave zeroed for next launch's hist
        int x = v;
        #pragma unroll
        for (int off = 1; off < 32; off <<= 1) {
            int y = __shfl_up_sync(0xFFFFFFFFu, x, off);
            if (lane >= off) x += y;
        }
        if (lane == 31) warp_sums[w] = x;
        __syncthreads();
        if (w == 0) {
            int s = warp_sums[lane];
            #pragma unroll
            for (int off = 1; off < 32; off <<= 1) {
                int y = __shfl_up_sync(0xFFFFFFFFu, s, off);
                if (lane >= off) s += y;
            }
            warp_sums[lane] = s;
        }
        __syncthreads();
        int warp_off = (w > 0) ? warp_sums[w - 1] : 0;
        int excl = x - v + warp_off;
        int rp = s_base + excl;
        if (i < N_NODES) { g_rowptr[i] = rp; g_cursor[i] = rp; }
        int total = warp_sums[31];
        __syncthreads();
        if (t == 0) s_base += total;
        __syncthreads();
    }
    if (threadIdx.x == 0) g_rowptr[N_NODES] = s_base;
}

__global__ void scatter_kernel(const int* __restrict__ src,
                               const int* __restrict__ dst) {
    int e4 = blockIdx.x * blockDim.x + threadIdx.x;
    if (e4 < N_EDGES / 4) {
        int4 d = ((const int4*)dst)[e4];
        int4 s = ((const int4*)src)[e4];
        g_esrc[atomicAdd(&g_cursor[d.x], 1)] = s.x;
        g_esrc[atomicAdd(&g_cursor[d.y], 1)] = s.y;
        g_esrc[atomicAdd(&g_cursor[d.z], 1)] = s.z;
        g_esrc[atomicAdd(&g_cursor[d.w], 1)] = s.w;
    }
}

// ---------------- GIN aggregation: warp/node, 8-edge unroll, f32x2 adds ------
__global__ void agg_kernel(const float* __restrict__ h,
                           const float* __restrict__ eps, int layer) {
    int warp = (blockIdx.x * blockDim.x + threadIdx.x) >> 5;
    int lane = threadIdx.x & 31;
    if (warp >= N_NODES) return;
    const ulonglong2* h2 = (const ulonglong2*)h;   // 16B per lane (4 floats)
    ulonglong2 sv = h2[(size_t)warp * 32 + lane];
    ull se2; DUP2(se2, 1.0f + eps[layer]);
    ull acc0, acc1;
    MUL2(acc0, sv.x, se2);
    MUL2(acc1, sv.y, se2);
    int e = g_rowptr[warp];
    int end = g_rowptr[warp + 1];
    // peel to 4-alignment so int4 index loads are 16B-aligned
    for (; e < end && (e & 3); e++) {
        ulonglong2 v = h2[(size_t)g_esrc[e] * 32 + lane];
        ADD2(acc0, acc0, v.x);
        ADD2(acc1, acc1, v.y);
    }
    for (; e + 8 <= end; e += 8) {
        int4 i0 = *(const int4*)&g_esrc[e];
        int4 i1 = *(const int4*)&g_esrc[e + 4];
        ulonglong2 v0 = h2[(size_t)i0.x * 32 + lane];
        ulonglong2 v1 = h2[(size_t)i0.y * 32 + lane];
        ulonglong2 v2 = h2[(size_t)i0.z * 32 + lane];
        ulonglong2 v3 = h2[(size_t)i0.w * 32 + lane];
        ulonglong2 v4 = h2[(size_t)i1.x * 32 + lane];
        ulonglong2 v5 = h2[(size_t)i1.y * 32 + lane];
        ulonglong2 v6 = h2[(size_t)i1.z * 32 + lane];
        ulonglong2 v7 = h2[(size_t)i1.w * 32 + lane];
        ull t0, t1, t2, t3;
        ADD2(t0, v0.x, v1.x); ADD2(t1, v2.x, v3.x);
        ADD2(t2, v4.x, v5.x); ADD2(t3, v6.x, v7.x);
        ADD2(t0, t0, t1);     ADD2(t2, t2, t3);
        ADD2(t0, t0, t2);     ADD2(acc0, acc0, t0);
        ADD2(t0, v0.y, v1.y); ADD2(t1, v2.y, v3.y);
        ADD2(t2, v4.y, v5.y); ADD2(t3, v6.y, v7.y);
        ADD2(t0, t0, t1);     ADD2(t2, t2, t3);
        ADD2(t0, t0, t2);     ADD2(acc1, acc1, t0);
    }
    if (e + 4 <= end) {
        int4 i0 = *(const int4*)&g_esrc[e];
        ulonglong2 v0 = h2[(size_t)i0.x * 32 + lane];
        ulonglong2 v1 = h2[(size_t)i0.y * 32 + lane];
        ulonglong2 v2 = h2[(size_t)i0.z * 32 + lane];
        ulonglong2 v3 = h2[(size_t)i0.w * 32 + lane];
        ull t0, t1;
        ADD2(t0, v0.x, v1.x); ADD2(t1, v2.x, v3.x);
        ADD2(t0, t0, t1);     ADD2(acc0, acc0, t0);
        ADD2(t0, v0.y, v1.y); ADD2(t1, v2.y, v3.y);
        ADD2(t0, t0, t1);     ADD2(acc1, acc1, t0);
        e += 4;
    }
    for (; e < end; e++) {
        ulonglong2 v = h2[(size_t)g_esrc[e] * 32 + lane];
        ADD2(acc0, acc0, v.x);
        ADD2(acc1, acc1, v.y);
    }
    ulonglong2 ov; ov.x = acc0; ov.y = acc1;
    ((ulonglong2*)g_agg)[(size_t)warp * 32 + lane] = ov;
}

// ---------------- HMMA fused MLP (split-bf16, 3-pass), 192 rows/block --------
#define TM       192
#define NTHREADS 384
#define A_LD_B   272
#define SM_AS_HI 0
#define SM_AS_LO 52224
#define SM_W_HI  104448
#define SM_W_LO  139264
#define MLP_SMEM 174080

__global__ __launch_bounds__(NTHREADS) void mma_mlp_kernel(
    float* __restrict__ hout, int mat1,
    const float* __restrict__ b1v,
    const float* __restrict__ gammav, const float* __restrict__ betav,
    const float* __restrict__ rmeanv, const float* __restrict__ rvarv,
    const float* __restrict__ b2v)
{
    extern __shared__ char sm[];
    __shared__ float sc[128], sh[128], sb2[128];

    int tid = threadIdx.x, wid = tid >> 5, lane = tid & 31;
    int row0 = blockIdx.x * TM;
    uint32_t base = smem_to_u32(sm);

    if (tid < 128) {
        float s = gammav[tid] * rsqrtf(rvarv[tid] + 1e-5f);
        sc[tid] = s;
        sh[tid] = (b1v[tid] - rmeanv[tid]) * s + betav[tid];
        sb2[tid] = b2v[tid];
    }

    // --- A fill: fp32 agg -> bf16 hi/lo, padded rows (192 x 32 float4) ------
    for (int i = tid; i < TM * 32; i += NTHREADS) {
        int r = i >> 5, c4 = i & 31;
        int gidx = row0 + r;
        float4 v = make_float4(0.f, 0.f, 0.f, 0.f);
        if (gidx < N_NODES) v = ((const float4*)g_agg)[(size_t)gidx * 32 + c4];
        __nv_bfloat162 h01 = __floats2bfloat162_rn(v.x, v.y);
        __nv_bfloat162 h23 = __floats2bfloat162_rn(v.z, v.w);
        __nv_bfloat162 l01 = __floats2bfloat162_rn(v.x - __bfloat162float(h01.x),
                                                   v.y - __bfloat162float(h01.y));
        __nv_bfloat162 l23 = __floats2bfloat162_rn(v.z - __bfloat162float(h23.x),
                                                   v.w - __bfloat162float(h23.y));
        uint2 uh = make_uint2(bf2_bits(h01), bf2_bits(h23));
        uint2 ul = make_uint2(bf2_bits(l01), bf2_bits(l23));
        *(uint2*)(sm + SM_AS_HI + r * A_LD_B + c4 * 8) = uh;
        *(uint2*)(sm + SM_AS_LO + r * A_LD_B + c4 * 8) = ul;
    }
    // --- W1 fill --------------------------------------------------------------
    {
        const float4* s1h = (const float4*)g_wimg_hi + (size_t)mat1 * 2048;
        const float4* s1l = (const float4*)g_wimg_lo + (size_t)mat1 * 2048;
        for (int i = tid; i < 2048; i += NTHREADS) {
            int n = i >> 4, c = i & 15;
            int off = n * A_LD_B + c * 16;
            *(float4*)(sm + SM_W_HI + off) = s1h[i];
            *(float4*)(sm + SM_W_LO + off) = s1l[i];
        }
    }
    __syncthreads();

    int m0 = wid * 16;
    int lrow = lane & 15, lkoff = (lane >> 4) << 3;          // A ldmatrix addressing
    uint32_t aAddrHi = base + SM_AS_HI + (m0 + lrow) * A_LD_B + lkoff * 2;
    uint32_t aAddrLo = base + SM_AS_LO + (m0 + lrow) * A_LD_B + lkoff * 2;
    int bn = lane & 7, bk = ((lane >> 3) & 1) << 3;          // B ldmatrix addressing

    uint32_t Ah[32], Al[32];
    #pragma unroll
    for (int kk = 0; kk < 8; kk++) {
        ldsm_x4(&Ah[kk * 4], aAddrHi + kk * 32);
        ldsm_x4(&Al[kk * 4], aAddrLo + kk * 32);
    }

    int erow = (lane >> 2);
    int ecl  = (lane & 3) * 2;

    // ---------------- GEMM1 + BN/ReLU/resplit -------------------------------
    #pragma unroll 1
    for (int nt = 0; nt < 16; nt++) {
        float c[4] = {0.f, 0.f, 0.f, 0.f};
        uint32_t bAddrHi = base + SM_W_HI + (nt * 8 + bn) * A_LD_B + bk * 2;
        uint32_t bAddrLo = base + SM_W_LO + (nt * 8 + bn) * A_LD_B + bk * 2;
        #pragma unroll
        for (int kk = 0; kk < 8; kk++) {
            uint32_t bh[2], bl[2];
            ldsm_x2(bh, bAddrHi + kk * 32);
            ldsm_x2(bl, bAddrLo + kk * 32);
            mma_bf16(c, &Ah[kk * 4], bh);
            mma_bf16(c, &Ah[kk * 4], bl);
            mma_bf16(c, &Al[kk * 4], bh);
        }
        int col = nt * 8 + ecl;
        float s0 = sc[col], s1 = sc[col + 1], t0 = sh[col], t1 = sh[col + 1];
        #pragma unroll
        for (int half = 0; half < 2; half++) {
            int r = m0 + erow + half * 8;
            float z0 = fmaxf(fmaf(c[half * 2 + 0], s0, t0), 0.f);
            float z1 = fmaxf(fmaf(c[half * 2 + 1], s1, t1), 0.f);
            __nv_bfloat162 zh = __floats2bfloat162_rn(z0, z1);
            __nv_bfloat162 zl = __floats2bfloat162_rn(z0 - __bfloat162float(zh.x),
                                                      z1 - __bfloat162float(zh.y));
            *(uint32_t*)(sm + SM_AS_HI + r * A_LD_B + col * 2) = bf2_bits(zh);
            *(uint32_t*)(sm + SM_AS_LO + r * A_LD_B + col * 2) = bf2_bits(zl);
        }
    }

    // ---- swap W1 -> W2 (all warps must finish reading W1 first) ------------
    __syncthreads();
    {
        int mat2 = mat1 + 1;
        const float4* s2h = (const float4*)g_wimg_hi + (size_t)mat2 * 2048;
        const float4* s2l = (const float4*)g_wimg_lo + (size_t)mat2 * 2048;
        for (int i = tid; i < 2048; i += NTHREADS) {
            int n = i >> 4, c = i & 15;
            int off = n * A_LD_B + c * 16;
            *(float4*)(sm + SM_W_HI + off) = s2h[i];
            *(float4*)(sm + SM_W_LO + off) = s2l[i];
        }
    }
    __syncthreads();

    // reload A frags (z)
    #pragma unroll
    for (int kk = 0; kk < 8; kk++) {
        ldsm_x4(&Ah[kk * 4], aAddrHi + kk * 32);
        ldsm_x4(&Al[kk * 4], aAddrLo + kk * 32);
    }

    // ---------------- GEMM2 + bias/ReLU/store -------------------------------
    #pragma unroll 1
    for (int nt = 0; nt < 16; nt++) {
        float c[4] = {0.f, 0.f, 0.f, 0.f};
        uint32_t bAddrHi = base + SM_W_HI + (nt * 8 + bn) * A_LD_B + bk * 2;
        uint32_t bAddrLo = base + SM_W_LO + (nt * 8 + bn) * A_LD_B + bk * 2;
        #pragma unroll
        for (int kk = 0; kk < 8; kk++) {
            uint32_t bh[2], bl[2];
            ldsm_x2(bh, bAddrHi + kk * 32);
            ldsm_x2(bl, bAddrLo + kk * 32);
            mma_bf16(c, &Ah[kk * 4], bh);
            mma_bf16(c, &Ah[kk * 4], bl);
            mma_bf16(c, &Al[kk * 4], bh);
        }
        int col = nt * 8 + ecl;
        float b0 = sb2[col], b1 = sb2[col + 1];
        #pragma unroll
        for (int half = 0; half < 2; half++) {
            int grow = row0 + m0 + erow + half * 8;
            if (grow < N_NODES) {
                float2 ov;
                ov.x = fmaxf(c[half * 2 + 0] + b0, 0.f);
                ov.y = fmaxf(c[half * 2 + 1] + b1, 0.f);
                *(float2*)&hout[(size_t)grow * DF + col] = ov;
            }
        }
    }
}

// ---------------- fused pool (sorted batch) + head ---------------------------
__global__ __launch_bounds__(128) void pool_out_kernel(
    const float* __restrict__ h, const int* __restrict__ batch,
    const float* __restrict__ Wout, const float* __restrict__ bout,
    float* __restrict__ out)
{
    __shared__ float sp[DF];
    int g = blockIdx.x;
    int t = threadIdx.x;

    int lo = 0, hi = N_NODES;
    while (lo < hi) { int m = (lo + hi) >> 1; if (batch[m] < g) lo = m + 1; else hi = m; }
    int start = lo;
    hi = N_NODES;
    while (lo < hi) { int m = (lo + hi) >> 1; if (batch[m] < g + 1) lo = m + 1; else hi = m; }
    int end = lo;

    float s = 0.f;
    for (int n = start; n < end; n++) s += h[(size_t)n * DF + t];
    float cnt = (float)(end - start);
    sp[t] = s / fmaxf(cnt, 1.0f);
    __syncthreads();

    if (t < D_OUT) {
        float acc = bout[t];
        #pragma unroll 8
        for (int d = 0; d < DF; d++) acc += sp[d] * Wout[d * D_OUT + t];
        out[g * D_OUT + t] = acc;
    }
}

// ---------------- launch ------------------------------------------------------
extern "C" void kernel_launch(void* const* d_in, const int* in_sizes, int n_in,
                              void* d_out, int out_size) {
    const float* x     = (const float*)d_in[0];
    const int*   ei    = (const int*)d_in[1];     // [2][N_EDGES], int32
    const int*   batch = (const int*)d_in[2];     // int32 (sorted)
    const float* W1    = (const float*)d_in[3];
    const float* b1    = (const float*)d_in[4];
    const float* gamma = (const float*)d_in[5];
    const float* beta  = (const float*)d_in[6];
    const float* rmean = (const float*)d_in[7];
    const float* rvar  = (const float*)d_in[8];
    const float* W2    = (const float*)d_in[9];
    const float* b2    = (const float*)d_in[10];
    const float* eps   = (const float*)d_in[11];
    const float* Wout  = (const float*)d_in[12];
    const float* bout  = (const float*)d_in[13];
    float* out = (float*)d_out;

    cudaFuncSetAttribute(mma_mlp_kernel, cudaFuncAttributeMaxDynamicSharedMemorySize,
                         MLP_SMEM);

    float *h0_dev;
    cudaGetSymbolAddress((void**)&h0_dev, g_h0);

    const int* src = ei;
    const int* dst = ei + N_EDGES;

    histprep_kernel<<<(N_EDGES / 4 + 255) / 256, 256>>>(dst, W1, W2);
    scan_kernel<<<1, 1024>>>();
    scatter_kernel<<<(N_EDGES / 4 + 255) / 256, 256>>>(src, dst);

    const float* hin = x;
    int mlp_blocks = (N_NODES + TM - 1) / TM;
    for (int l = 0; l < 3; l++) {
        agg_kernel<<<(N_NODES * 32 + 255) / 256, 256>>>(hin, eps, l);
        mma_mlp_kernel<<<mlp_blocks, NTHREADS, MLP_SMEM>>>(
            h0_dev, l * 2,
            b1 + l * DF, gamma + l * DF, beta + l * DF,
            rmean + l * DF, rvar + l * DF, b2 + l * DF);
        hin = h0_dev;
    }

    pool_out_kernel<<<N_GRAPHS, 128>>>(hin, batch, Wout, bout, out);
}

// round 14
// speedup vs baseline: 1.1397x; 1.1397x over previous
#include <cuda_runtime.h>
#include <cuda_bf16.h>
#include <cstdint>

#define N_NODES 25000
#define N_EDGES 400000
#define DF      128
#define N_GRAPHS 512
#define D_OUT   10

// ---------------- scratch (device globals; no runtime alloc allowed) --------
// g_deg is zero at module load; re-zeroed by pool_out_kernel each launch.
__device__ __align__(16) int   g_deg[N_NODES];
__device__ __align__(16) int   g_rowptr[N_NODES];
__device__ __align__(16) int   g_cursor[N_NODES];
__device__ __align__(16) int   g_esrc[N_EDGES];
__device__             int     g_total;
__device__ __align__(16) float g_agg[N_NODES * DF];
__device__ __align__(16) float g_h0[N_NODES * DF];
// bf16 hi/lo weight images, [n][k] row-major, 6 matrices (layer*2 + {W1,W2})
__device__ __align__(16) unsigned short g_wimg_hi[6 * 16384];
__device__ __align__(16) unsigned short g_wimg_lo[6 * 16384];

// ---------------- helpers -----------------------------------------------------
__device__ __forceinline__ uint32_t smem_to_u32(const void* p) {
    uint32_t a;
    asm("{ .reg .u64 t; cvta.to.shared.u64 t, %1; cvt.u32.u64 %0, t; }"
        : "=r"(a) : "l"(p));
    return a;
}
__device__ __forceinline__ void ldsm_x4(uint32_t* r, uint32_t addr) {
    asm volatile("ldmatrix.sync.aligned.m8n8.x4.shared.b16 {%0,%1,%2,%3}, [%4];"
        : "=r"(r[0]), "=r"(r[1]), "=r"(r[2]), "=r"(r[3]) : "r"(addr));
}
__device__ __forceinline__ void ldsm_x2(uint32_t* r, uint32_t addr) {
    asm volatile("ldmatrix.sync.aligned.m8n8.x2.shared.b16 {%0,%1}, [%2];"
        : "=r"(r[0]), "=r"(r[1]) : "r"(addr));
}
__device__ __forceinline__ void mma_bf16(float* c, const uint32_t* a, const uint32_t* b) {
    asm volatile("mma.sync.aligned.m16n8k16.row.col.f32.bf16.bf16.f32 "
        "{%0,%1,%2,%3}, {%4,%5,%6,%7}, {%8,%9}, {%0,%1,%2,%3};"
        : "+f"(c[0]), "+f"(c[1]), "+f"(c[2]), "+f"(c[3])
        : "r"(a[0]), "r"(a[1]), "r"(a[2]), "r"(a[3]), "r"(b[0]), "r"(b[1]));
}
__device__ __forceinline__ uint32_t bf2_bits(__nv_bfloat162 v) {
    return *reinterpret_cast<uint32_t*>(&v);
}

// ---------------- prep: zero counter + weight hi/lo split images -------------
__global__ void prep_kernel(const float* __restrict__ W1,
                            const float* __restrict__ W2) {
    int e = blockIdx.x * blockDim.x + threadIdx.x;
    if (e == 0) g_total = 0;
    if (e < 6 * 16384) {
        int mat = e >> 14, r = e & 16383;
        int k = r & 127, n = r >> 7;
        int layer = mat >> 1;
        const float* W = (mat & 1) ? W2 : W1;
        float v = W[layer * 16384 + k * 128 + n];
        __nv_bfloat16 hb = __float2bfloat16(v);
        __nv_bfloat16 lb = __float2bfloat16(v - __bfloat162float(hb));
        g_wimg_hi[mat * 16384 + n * 128 + k] = *reinterpret_cast<unsigned short*>(&hb);
        g_wimg_lo[mat * 16384 + n * 128 + k] = *reinterpret_cast<unsigned short*>(&lb);
    }
}

// ---------------- CSR build: histogram -> atomic base alloc -> scatter -------
__global__ void hist_kernel(const int* __restrict__ dst) {
    int e4 = blockIdx.x * blockDim.x + threadIdx.x;
    if (e4 < N_EDGES / 4) {
        int4 d = ((const int4*)dst)[e4];
        atomicAdd(&g_deg[d.x], 1);
        atomicAdd(&g_deg[d.y], 1);
        atomicAdd(&g_deg[d.z], 1);
        atomicAdd(&g_deg[d.w], 1);
    }
}

// Grid-parallel base allocation: bucket bases need NOT be in node order —
// agg uses [start, start + deg) only. Block prefix + one atomicAdd per block.
__global__ __launch_bounds__(256) void alloc_kernel() {
    __shared__ int warp_sums[8];
    __shared__ int s_base;
    int t = threadIdx.x, lane = t & 31, w = t >> 5;
    int i = blockIdx.x * 256 + t;
    int v = (i < N_NODES) ? g_deg[i] : 0;
    int x = v;
    #pragma unroll
    for (int off = 1; off < 32; off <<= 1) {
        int y = __shfl_up_sync(0xFFFFFFFFu, x, off);
        if (lane >= off) x += y;
    }
    if (lane == 31) warp_sums[w] = x;
    __syncthreads();
    if (w == 0 && lane < 8) {
        int s = warp_sums[lane];
        #pragma unroll
        for (int off = 1; off < 8; off <<= 1) {
            int y = __shfl_up_sync(0xFFu, s, off);
            if (lane >= off) s += y;
        }
        warp_sums[lane] = s;
        if (lane == 7) s_base = atomicAdd(&g_total, s);
    }
    __syncthreads();
    int warp_off = (w > 0) ? warp_sums[w - 1] : 0;
    int base = s_base + warp_off + x - v;   // exclusive prefix within block
    if (i < N_NODES) { g_rowptr[i] = base; g_cursor[i] = base; }
}

__global__ void scatter_kernel(const int* __restrict__ src,
                               const int* __restrict__ dst) {
    int e4 = blockIdx.x * blockDim.x + threadIdx.x;
    if (e4 < N_EDGES / 4) {
        int4 d = ((const int4*)dst)[e4];
        int4 s = ((const int4*)src)[e4];
        g_esrc[atomicAdd(&g_cursor[d.x], 1)] = s.x;
        g_esrc[atomicAdd(&g_cursor[d.y], 1)] = s.y;
        g_esrc[atomicAdd(&g_cursor[d.z], 1)] = s.z;
        g_esrc[atomicAdd(&g_cursor[d.w], 1)] = s.w;
    }
}

// ---------------- GIN aggregation: one warp per node, 8-edge unroll ----------
__global__ void agg_kernel(const float* __restrict__ h,
                           const float* __restrict__ eps, int layer) {
    int warp = (blockIdx.x * blockDim.x + threadIdx.x) >> 5;
    int lane = threadIdx.x & 31;
    if (warp >= N_NODES) return;
    float se = 1.0f + eps[layer];
    const float4* h4 = (const float4*)h;
    float4 acc = h4[(size_t)warp * 32 + lane];
    acc.x *= se; acc.y *= se; acc.z *= se; acc.w *= se;
    int e = g_rowptr[warp];
    int end = e + g_deg[warp];
    // peel to 4-alignment so int4 index loads are 16B-aligned
    for (; e < end && (e & 3); e++) {
        int s = g_esrc[e];
        float4 v = h4[(size_t)s * 32 + lane];
        acc.x += v.x; acc.y += v.y; acc.z += v.z; acc.w += v.w;
    }
    for (; e + 8 <= end; e += 8) {
        int4 i0 = *(const int4*)&g_esrc[e];
        int4 i1 = *(const int4*)&g_esrc[e + 4];
        float4 v0 = h4[(size_t)i0.x * 32 + lane];
        float4 v1 = h4[(size_t)i0.y * 32 + lane];
        float4 v2 = h4[(size_t)i0.z * 32 + lane];
        float4 v3 = h4[(size_t)i0.w * 32 + lane];
        float4 v4 = h4[(size_t)i1.x * 32 + lane];
        float4 v5 = h4[(size_t)i1.y * 32 + lane];
        float4 v6 = h4[(size_t)i1.z * 32 + lane];
        float4 v7 = h4[(size_t)i1.w * 32 + lane];
        acc.x += ((v0.x + v1.x) + (v2.x + v3.x)) + ((v4.x + v5.x) + (v6.x + v7.x));
        acc.y += ((v0.y + v1.y) + (v2.y + v3.y)) + ((v4.y + v5.y) + (v6.y + v7.y));
        acc.z += ((v0.z + v1.z) + (v2.z + v3.z)) + ((v4.z + v5.z) + (v6.z + v7.z));
        acc.w += ((v0.w + v1.w) + (v2.w + v3.w)) + ((v4.w + v5.w) + (v6.w + v7.w));
    }
    if (e + 4 <= end) {
        int4 i0 = *(const int4*)&g_esrc[e];
        float4 v0 = h4[(size_t)i0.x * 32 + lane];
        float4 v1 = h4[(size_t)i0.y * 32 + lane];
        float4 v2 = h4[(size_t)i0.z * 32 + lane];
        float4 v3 = h4[(size_t)i0.w * 32 + lane];
        acc.x += (v0.x + v1.x) + (v2.x + v3.x);
        acc.y += (v0.y + v1.y) + (v2.y + v3.y);
        acc.z += (v0.z + v1.z) + (v2.z + v3.z);
        acc.w += (v0.w + v1.w) + (v2.w + v3.w);
        e += 4;
    }
    for (; e < end; e++) {
        int s = g_esrc[e];
        float4 v = h4[(size_t)s * 32 + lane];
        acc.x += v.x; acc.y += v.y; acc.z += v.z; acc.w += v.w;
    }
    ((float4*)g_agg)[(size_t)warp * 32 + lane] = acc;
}

// ---------------- HMMA fused MLP (split-bf16, 3-pass), 192 rows/block --------
#define TM       192
#define NTHREADS 384
#define A_LD_B   272
#define SM_AS_HI 0
#define SM_AS_LO 52224
#define SM_W_HI  104448
#define SM_W_LO  139264
#define MLP_SMEM 174080

__global__ __launch_bounds__(NTHREADS) void mma_mlp_kernel(
    float* __restrict__ hout, int mat1,
    const float* __restrict__ b1v,
    const float* __restrict__ gammav, const float* __restrict__ betav,
    const float* __restrict__ rmeanv, const float* __restrict__ rvarv,
    const float* __restrict__ b2v)
{
    extern __shared__ char sm[];
    __shared__ float sc[128], sh[128], sb2[128];

    int tid = threadIdx.x, wid = tid >> 5, lane = tid & 31;
    int row0 = blockIdx.x * TM;
    uint32_t base = smem_to_u32(sm);

    if (tid < 128) {
        float s = gammav[tid] * rsqrtf(rvarv[tid] + 1e-5f);
        sc[tid] = s;
        sh[tid] = (b1v[tid] - rmeanv[tid]) * s + betav[tid];
        sb2[tid] = b2v[tid];
    }

    // --- A fill: fp32 agg -> bf16 hi/lo, padded rows (192 x 32 float4) ------
    for (int i = tid; i < TM * 32; i += NTHREADS) {
        int r = i >> 5, c4 = i & 31;
        int gidx = row0 + r;
        float4 v = make_float4(0.f, 0.f, 0.f, 0.f);
        if (gidx < N_NODES) v = ((const float4*)g_agg)[(size_t)gidx * 32 + c4];
        __nv_bfloat162 h01 = __floats2bfloat162_rn(v.x, v.y);
        __nv_bfloat162 h23 = __floats2bfloat162_rn(v.z, v.w);
        __nv_bfloat162 l01 = __floats2bfloat162_rn(v.x - __bfloat162float(h01.x),
                                                   v.y - __bfloat162float(h01.y));
        __nv_bfloat162 l23 = __floats2bfloat162_rn(v.z - __bfloat162float(h23.x),
                                                   v.w - __bfloat162float(h23.y));
        uint2 uh = make_uint2(bf2_bits(h01), bf2_bits(h23));
        uint2 ul = make_uint2(bf2_bits(l01), bf2_bits(l23));
        *(uint2*)(sm + SM_AS_HI + r * A_LD_B + c4 * 8) = uh;
        *(uint2*)(sm + SM_AS_LO + r * A_LD_B + c4 * 8) = ul;
    }
    // --- W1 fill --------------------------------------------------------------
    {
        const float4* s1h = (const float4*)g_wimg_hi + (size_t)mat1 * 2048;
        const float4* s1l = (const float4*)g_wimg_lo + (size_t)mat1 * 2048;
        for (int i = tid; i < 2048; i += NTHREADS) {
            int n = i >> 4, c = i & 15;
            int off = n * A_LD_B + c * 16;
            *(float4*)(sm + SM_W_HI + off) = s1h[i];
            *(float4*)(sm + SM_W_LO + off) = s1l[i];
        }
    }
    __syncthreads();

    int m0 = wid * 16;
    int lrow = lane & 15, lkoff = (lane >> 4) << 3;          // A ldmatrix addressing
    uint32_t aAddrHi = base + SM_AS_HI + (m0 + lrow) * A_LD_B + lkoff * 2;
    uint32_t aAddrLo = base + SM_AS_LO + (m0 + lrow) * A_LD_B + lkoff * 2;
    int bn = lane & 7, bk = ((lane >> 3) & 1) << 3;          // B ldmatrix addressing

    uint32_t Ah[32], Al[32];
    #pragma unroll
    for (int kk = 0; kk < 8; kk++) {
        ldsm_x4(&Ah[kk * 4], aAddrHi + kk * 32);
        ldsm_x4(&Al[kk * 4], aAddrLo + kk * 32);
    }

    int erow = (lane >> 2);
    int ecl  = (lane & 3) * 2;

    // ---------------- GEMM1 + BN/ReLU/resplit -------------------------------
    #pragma unroll 1
    for (int nt = 0; nt < 16; nt++) {
        float c[4] = {0.f, 0.f, 0.f, 0.f};
        uint32_t bAddrHi = base + SM_W_HI + (nt * 8 + bn) * A_LD_B + bk * 2;
        uint32_t bAddrLo = base + SM_W_LO + (nt * 8 + bn) * A_LD_B + bk * 2;
        #pragma unroll
        for (int kk = 0; kk < 8; kk++) {
            uint32_t bh[2], bl[2];
            ldsm_x2(bh, bAddrHi + kk * 32);
            ldsm_x2(bl, bAddrLo + kk * 32);
            mma_bf16(c, &Ah[kk * 4], bh);
            mma_bf16(c, &Ah[kk * 4], bl);
            mma_bf16(c, &Al[kk * 4], bh);
        }
        int col = nt * 8 + ecl;
        float s0 = sc[col], s1 = sc[col + 1], t0 = sh[col], t1 = sh[col + 1];
        #pragma unroll
        for (int half = 0; half < 2; half++) {
            int r = m0 + erow + half * 8;
            float z0 = fmaxf(fmaf(c[half * 2 + 0], s0, t0), 0.f);
            float z1 = fmaxf(fmaf(c[half * 2 + 1], s1, t1), 0.f);
            __nv_bfloat162 zh = __floats2bfloat162_rn(z0, z1);
            __nv_bfloat162 zl = __floats2bfloat162_rn(z0 - __bfloat162float(zh.x),
                                                      z1 - __bfloat162float(zh.y));
            *(uint32_t*)(sm + SM_AS_HI + r * A_LD_B + col * 2) = bf2_bits(zh);
            *(uint32_t*)(sm + SM_AS_LO + r * A_LD_B + col * 2) = bf2_bits(zl);
        }
    }

    // ---- swap W1 -> W2 (all warps must finish reading W1 first) ------------
    __syncthreads();
    {
        int mat2 = mat1 + 1;
        const float4* s2h = (const float4*)g_wimg_hi + (size_t)mat2 * 2048;
        const float4* s2l = (const float4*)g_wimg_lo + (size_t)mat2 * 2048;
        for (int i = tid; i < 2048; i += NTHREADS) {
            int n = i >> 4, c = i & 15;
            int off = n * A_LD_B + c * 16;
            *(float4*)(sm + SM_W_HI + off) = s2h[i];
            *(float4*)(sm + SM_W_LO + off) = s2l[i];
        }
    }
    __syncthreads();

    // reload A frags (z)
    #pragma unroll
    for (int kk = 0; kk < 8; kk++) {
        ldsm_x4(&Ah[kk * 4], aAddrHi + kk * 32);
        ldsm_x4(&Al[kk * 4], aAddrLo + kk * 32);
    }

    // ---------------- GEMM2 + bias/ReLU/store -------------------------------
    #pragma unroll 1
    for (int nt = 0; nt < 16; nt++) {
        float c[4] = {0.f, 0.f, 0.f, 0.f};
        uint32_t bAddrHi = base + SM_W_HI + (nt * 8 + bn) * A_LD_B + bk * 2;
        uint32_t bAddrLo = base + SM_W_LO + (nt * 8 + bn) * A_LD_B + bk * 2;
        #pragma unroll
        for (int kk = 0; kk < 8; kk++) {
            uint32_t bh[2], bl[2];
            ldsm_x2(bh, bAddrHi + kk * 32);
            ldsm_x2(bl, bAddrLo + kk * 32);
            mma_bf16(c, &Ah[kk * 4], bh);
            mma_bf16(c, &Ah[kk * 4], bl);
            mma_bf16(c, &Al[kk * 4], bh);
        }
        int col = nt * 8 + ecl;
        float b0 = sb2[col], b1 = sb2[col + 1];
        #pragma unroll
        for (int half = 0; half < 2; half++) {
            int grow = row0 + m0 + erow + half * 8;
            if (grow < N_NODES) {
                float2 ov;
                ov.x = fmaxf(c[half * 2 + 0] + b0, 0.f);
                ov.y = fmaxf(c[half * 2 + 1] + b1, 0.f);
                *(float2*)&hout[(size_t)grow * DF + col] = ov;
            }
        }
    }
}

// ---------------- fused pool (sorted batch) + head + deg dezero --------------
__global__ __launch_bounds__(128) void pool_out_kernel(
    const float* __restrict__ h, const int* __restrict__ batch,
    const float* __restrict__ Wout, const float* __restrict__ bout,
    float* __restrict__ out)
{
    __shared__ float sp[DF];
    int g = blockIdx.x;
    int t = threadIdx.x;

    // re-zero deg for the next launch (65536 threads >= N_NODES)
    int zi = g * 128 + t;
    if (zi < N_NODES) g_deg[zi] = 0;

    int lo = 0, hi = N_NODES;
    while (lo < hi) { int m = (lo + hi) >> 1; if (batch[m] < g) lo = m + 1; else hi = m; }
    int start = lo;
    hi = N_NODES;
    while (lo < hi) { int m = (lo + hi) >> 1; if (batch[m] < g + 1) lo = m + 1; else hi = m; }
    int end = lo;

    float s = 0.f;
    for (int n = start; n < end; n++) s += h[(size_t)n * DF + t];
    float cnt = (float)(end - start);
    sp[t] = s / fmaxf(cnt, 1.0f);
    __syncthreads();

    if (t < D_OUT) {
        float acc = bout[t];
        #pragma unroll 8
        for (int d = 0; d < DF; d++) acc += sp[d] * Wout[d * D_OUT + t];
        out[g * D_OUT + t] = acc;
    }
}

// ---------------- launch ------------------------------------------------------
extern "C" void kernel_launch(void* const* d_in, const int* in_sizes, int n_in,
                              void* d_out, int out_size) {
    const float* x     = (const float*)d_in[0];
    const int*   ei    = (const int*)d_in[1];     // [2][N_EDGES], int32
    const int*   batch = (const int*)d_in[2];     // int32 (sorted)
    const float* W1    = (const float*)d_in[3];
    const float* b1    = (const float*)d_in[4];
    const float* gamma = (const float*)d_in[5];
    const float* beta  = (const float*)d_in[6];
    const float* rmean = (const float*)d_in[7];
    const float* rvar  = (const float*)d_in[8];
    const float* W2    = (const float*)d_in[9];
    const float* b2    = (const float*)d_in[10];
    const float* eps   = (const float*)d_in[11];
    const float* Wout  = (const float*)d_in[12];
    const float* bout  = (const float*)d_in[13];
    float* out = (float*)d_out;

    cudaFuncSetAttribute(mma_mlp_kernel, cudaFuncAttributeMaxDynamicSharedMemorySize,
                         MLP_SMEM);

    float *h0_dev;
    cudaGetSymbolAddress((void**)&h0_dev, g_h0);

    const int* src = ei;
    const int* dst = ei + N_EDGES;

    prep_kernel<<<(6 * 16384 + 255) / 256, 256>>>(W1, W2);
    hist_kernel<<<(N_EDGES / 4 + 255) / 256, 256>>>(dst);
    alloc_kernel<<<(N_NODES + 255) / 256, 256>>>();
    scatter_kernel<<<(N_EDGES / 4 + 255) / 256, 256>>>(src, dst);

    const float* hin = x;
    int mlp_blocks = (N_NODES + TM - 1) / TM;
    for (int l = 0; l < 3; l++) {
        agg_kernel<<<(N_NODES * 32 + 255) / 256, 256>>>(hin, eps, l);
        mma_mlp_kernel<<<mlp_blocks, NTHREADS, MLP_SMEM>>>(
            h0_dev, l * 2,
            b1 + l * DF, gamma + l * DF, beta + l * DF,
            rmean + l * DF, rvar + l * DF, b2 + l * DF);
        hin = h0_dev;
    }

    pool_out_kernel<<<N_GRAPHS, 128>>>(hin, batch, Wout, bout, out);
}